// round 6
// baseline (speedup 1.0000x reference)
#include <cuda_runtime.h>
#include <math.h>

#define IMG   512
#define NVIEW 180
#define NPIX  (IMG * IMG)

typedef unsigned long long ull;

// Interleaved copy of both batch images: g_xi[y*512+x] = (batch0, batch1).
__device__ float2 g_xi[NPIX];
// Per-view (cos, sin) fp32, matching np.cos(np.linspace(0,pi,180,endpoint=False)).astype(f32)
__device__ float2 g_trig[NVIEW];

struct ViewShapes { unsigned char lw[NVIEW]; };

// ---- packed f32x2 helpers (sm_100+) ----
__device__ __forceinline__ ull pk(float lo, float hi) {
    ull r; asm("mov.b64 %0,{%1,%2};" : "=l"(r) : "f"(lo), "f"(hi)); return r;
}
__device__ __forceinline__ void upk(ull p, float& lo, float& hi) {
    asm("mov.b64 {%0,%1},%2;" : "=f"(lo), "=f"(hi) : "l"(p));
}
__device__ __forceinline__ ull mul2(ull a, ull b) {
    ull r; asm("mul.rn.f32x2 %0,%1,%2;" : "=l"(r) : "l"(a), "l"(b)); return r;
}
__device__ __forceinline__ ull add2(ull a, ull b) {
    ull r; asm("add.rn.f32x2 %0,%1,%2;" : "=l"(r) : "l"(a), "l"(b)); return r;
}
__device__ __forceinline__ ull fma2(ull a, ull b, ull c) {
    ull r; asm("fma.rn.f32x2 %0,%1,%2,%3;" : "=l"(r) : "l"(a), "l"(b), "l"(c)); return r;
}

// Interleave prep: x4 pixels per thread, vectorized 128-bit loads/stores.
__global__ __launch_bounds__(256) void prep_kernel(const float* __restrict__ x) {
    int i = blockIdx.x * blockDim.x + threadIdx.x;           // 16384 threads
    {
        const float4* a4 = (const float4*)x;                  // batch 0
        const float4* b4 = (const float4*)(x + NPIX);         // batch 1
        float4 a = a4[i];
        float4 b = b4[i];
        float4* o = (float4*)&g_xi[i * 4];
        o[0] = make_float4(a.x, b.x, a.y, b.y);
        o[1] = make_float4(a.z, b.z, a.w, b.w);
    }
    if (i < NVIEW) {
        double th = (double)i * (M_PI / 180.0);
        g_trig[i] = make_float2((float)cos(th), (float)sin(th));
    }
}

// Warp tile: W lanes along w, H = 32/W lanes along h; each warp makes 16
// outputs (NC = 16/W chunks). Uniform loop: 64 outer iterations, G = W/4
// h-steps each -> G*NC = 4 gathers in flight per thread (low reg pressure).
template<int LOGW>
__device__ __forceinline__ void radon_body(float* __restrict__ out, int v) {
    constexpr int W  = 1 << LOGW;
    constexpr int H  = 32 >> LOGW;
    constexpr int NC = 16 / W;     // w-chunks per warp
    constexpr int G  = W / 4;      // h-steps per outer iter (G*NC == 4)

    const int lane = threadIdx.x & 31;
    const int warp = threadIdx.x >> 5;
    const int wi   = lane & (W - 1);
    const int hi   = lane >> LOGW;
    const int wbase = (blockIdx.x << 6) + (warp << 4);

    const float2 cs = g_trig[v];
    const float c = cs.x, s = cs.y;
    const ull csP  = pk(s, c);          // (s, c)
    const ull sgnP = pk(-1.0f, 1.0f);   // gx = P - s*gy0 ; gy = S + c*gy0

    ull PS[NC], acc[NC];
    #pragma unroll
    for (int j = 0; j < NC; j++) {
        int w = wbase + j * W + wi;
        float gx0 = __fmaf_rn((float)w, 1.0f / 256.0f, -511.0f / 512.0f);  // exact
        PS[j] = pk(__fmul_rn(c, gx0), __fmul_rn(s, gx0));   // (P, S)
        acc[j] = 0ull;
    }

    // gy0 walks h = hi, hi+H, ... ; all values and increments exact in fp32
    float gy0 = __fmaf_rn((float)hi, 1.0f / 256.0f, -511.0f / 512.0f);
    ull gy0p = pk(gy0, gy0);
    const ull stepP = pk((float)H / 256.0f, (float)H / 256.0f);

    const float MAGIC = 12582912.0f;      // 1.5*2^23: magic round-half-even
    const float BOUND = 12583424.0f;      // MAGIC + 512

    #pragma unroll 1
    for (int to = 0; to < 64; to++) {
        #pragma unroll
        for (int g = 0; g < G; g++) {
            ull qp = mul2(gy0p, csP);         // (s*gy0, c*gy0), each rounded once
            gy0p = add2(gy0p, stepP);         // exact
            #pragma unroll
            for (int j = 0; j < NC; j++) {
                ull gp = fma2(qp, sgnP, PS[j]);   // (fl(P - s*gy0), fl(S + c*gy0))
                float gx, gy; upk(gp, gx, gy);
                gx = fmaxf(gx, -1.0f);            // lower clamp semantically required
                gy = fmaxf(gy, -1.0f);            // (upper clamp provably redundant)
                // ((g+1)*512-1)*0.5 == fma(g+1,256,-0.5) exactly; +MAGIC = rint(ties-even)
                float rx = __fadd_rn(__fmaf_rn(__fadd_rn(gx, 1.0f), 256.0f, -0.5f), MAGIC);
                float ry = __fadd_rn(__fmaf_rn(__fadd_rn(gy, 1.0f), 256.0f, -0.5f), MAGIC);
                bool ok = fmaxf(rx, ry) < BOUND;  // ix,iy >= 0 guaranteed by clamp
                // iy*512 + ix directly from magic bit patterns (mod 2^32)
                unsigned idx = (unsigned)__float_as_int(ry) * 512u
                             + (unsigned)__float_as_int(rx)
                             - 0x4B400000u * 513u;
                ull val = 0ull;
                if (ok) val = __ldg((const ull*)((const char*)g_xi + (size_t)idx * 8u));
                acc[j] = add2(acc[j], val);
            }
        }
    }

    // reduce over the H h-lanes of each chunk, then write
    #pragma unroll
    for (int j = 0; j < NC; j++) {
        float a0, a1; upk(acc[j], a0, a1);
        #pragma unroll
        for (int off = W; off < 32; off <<= 1) {
            a0 += __shfl_xor_sync(0xffffffffu, a0, off);
            a1 += __shfl_xor_sync(0xffffffffu, a1, off);
        }
        if (hi == 0) {
            int w = wbase + j * W + wi;
            out[v * IMG + w]               = a0 * (1.0f / 512.0f);
            out[NVIEW * IMG + v * IMG + w] = a1 * (1.0f / 512.0f);
        }
    }
}

// Single fat launch: all 180 views; per-block uniform dispatch on tile shape.
// 1440 blocks vs 12 blocks/SM * 148 SMs = 1776 slots: one wave with slack.
__global__ __launch_bounds__(128, 12) void radon_kernel(float* __restrict__ out, ViewShapes sh) {
    const int v = blockIdx.y;
    switch (sh.lw[v]) {
        case 2: radon_body<2>(out, v); break;
        case 3: radon_body<3>(out, v); break;
        default: radon_body<4>(out, v); break;
    }
}

extern "C" void kernel_launch(void* const* d_in, const int* in_sizes, int n_in,
                              void* d_out, int out_size) {
    const float* x = (const float*)d_in[0];
    float* out = (float*)d_out;

    prep_kernel<<<NPIX / 4 / 256, 256>>>(x);

    // Host-side per-view tile-shape selection (perf-only; any shape is correct).
    ViewShapes sh;
    for (int v = 0; v < NVIEW; v++) {
        double th = (double)v * (M_PI / 180.0);
        double ac = fabs(cos(th)), as = fabs(sin(th));
        int best = 2; double bestcost = 1e30;
        for (int lw = 2; lw <= 4; lw++) {
            double W = (double)(1 << lw), H = 32.0 / W;
            double rows = W * as + H * ac + 1.0;
            double segB = (W * ac + H * as) * 8.0 + 8.0;
            double cost = rows * (1.0 + segB / 128.0);
            if (cost < bestcost) { bestcost = cost; best = lw; }
        }
        sh.lw[v] = (unsigned char)best;
    }

    dim3 grid(IMG / 64, NVIEW);
    radon_kernel<<<grid, 128>>>(out, sh);
}

// round 7
// speedup vs baseline: 1.1046x; 1.1046x over previous
#include <cuda_runtime.h>
#include <math.h>

#define IMG   512
#define NVIEW 180
#define NPIX  (IMG * IMG)

typedef unsigned long long ull;

// Interleaved copy of both batch images: g_xi[y*512+x] = (batch0, batch1).
__device__ float2 g_xi[NPIX];
// Per-view (cos, sin) fp32, matching np.cos(np.linspace(0,pi,180,endpoint=False)).astype(f32)
__device__ float2 g_trig[NVIEW];

struct ViewShapes { unsigned char lw[NVIEW]; };

// ---- packed f32x2 helpers (sm_100+) ----
__device__ __forceinline__ ull pk(float lo, float hi) {
    ull r; asm("mov.b64 %0,{%1,%2};" : "=l"(r) : "f"(lo), "f"(hi)); return r;
}
__device__ __forceinline__ void upk(ull p, float& lo, float& hi) {
    asm("mov.b64 {%0,%1},%2;" : "=f"(lo), "=f"(hi) : "l"(p));
}
__device__ __forceinline__ ull mul2(ull a, ull b) {
    ull r; asm("mul.rn.f32x2 %0,%1,%2;" : "=l"(r) : "l"(a), "l"(b)); return r;
}
__device__ __forceinline__ ull add2(ull a, ull b) {
    ull r; asm("add.rn.f32x2 %0,%1,%2;" : "=l"(r) : "l"(a), "l"(b)); return r;
}
__device__ __forceinline__ ull fma2(ull a, ull b, ull c) {
    ull r; asm("fma.rn.f32x2 %0,%1,%2,%3;" : "=l"(r) : "l"(a), "l"(b), "l"(c)); return r;
}

// Interleave prep: 4 pixels per thread, vectorized 128-bit loads/stores.
__global__ __launch_bounds__(256) void prep_kernel(const float* __restrict__ x) {
    int i = blockIdx.x * blockDim.x + threadIdx.x;           // 16384 threads
    {
        const float4* a4 = (const float4*)x;                  // batch 0
        const float4* b4 = (const float4*)(x + NPIX);         // batch 1
        float4 a = a4[i];
        float4 b = b4[i];
        float4* o = (float4*)&g_xi[i * 4];
        o[0] = make_float4(a.x, b.x, a.y, b.y);
        o[1] = make_float4(a.z, b.z, a.w, b.w);
    }
    if (i < NVIEW) {
        double th = (double)i * (M_PI / 180.0);
        g_trig[i] = make_float2((float)cos(th), (float)sin(th));
    }
}

// Warp tile: W lanes along w, H = 32/W lanes along h; each warp makes 16
// outputs (NC = 16/W chunks). Uniform loop: 64 outer iterations, G = W/4
// h-steps each -> G*NC = 4 gathers in flight per thread.
template<int LOGW>
__device__ __forceinline__ void radon_body(float* __restrict__ out, int v) {
    constexpr int W  = 1 << LOGW;
    constexpr int H  = 32 >> LOGW;
    constexpr int NC = 16 / W;     // w-chunks per warp
    constexpr int G  = W / 4;      // h-steps per outer iter (G*NC == 4)

    const int lane = threadIdx.x & 31;
    const int warp = threadIdx.x >> 5;
    const int wi   = lane & (W - 1);
    const int hi   = lane >> LOGW;
    const int wbase = (blockIdx.x << 6) + (warp << 4);

    const float2 cs = g_trig[v];
    const float c = cs.x, s = cs.y;
    const ull csP  = pk(s, c);          // (s, c)
    const ull sgnP = pk(-1.0f, 1.0f);   // gx = P - s*gy0 ; gy = S + c*gy0

    ull PS[NC], acc[NC];
    #pragma unroll
    for (int j = 0; j < NC; j++) {
        int w = wbase + j * W + wi;
        float gx0 = __fmaf_rn((float)w, 1.0f / 256.0f, -511.0f / 512.0f);  // exact
        PS[j] = pk(__fmul_rn(c, gx0), __fmul_rn(s, gx0));   // (P, S)
        acc[j] = 0ull;
    }

    // gy0 walks h = hi, hi+H, ... ; all values and increments exact in fp32
    float gy0 = __fmaf_rn((float)hi, 1.0f / 256.0f, -511.0f / 512.0f);
    ull gy0p = pk(gy0, gy0);
    const ull stepP = pk((float)H / 256.0f, (float)H / 256.0f);

    const float MAGIC = 12582912.0f;      // 1.5*2^23: magic round-half-even
    const float BOUND = 12583424.0f;      // MAGIC + 512
    const ull ONE2 = pk(1.0f, 1.0f);
    const ull C256 = pk(256.0f, 256.0f);
    const ull MH2  = pk(-0.5f, -0.5f);
    const ull MAG2 = pk(MAGIC, MAGIC);

    #pragma unroll 1
    for (int to = 0; to < 64; to++) {
        #pragma unroll
        for (int g = 0; g < G; g++) {
            ull qp = mul2(gy0p, csP);         // (s*gy0, c*gy0), each rounded once
            gy0p = add2(gy0p, stepP);         // exact
            #pragma unroll
            for (int j = 0; j < NC; j++) {
                ull gp = fma2(qp, sgnP, PS[j]);   // (fl(P - s*gy0), fl(S + c*gy0))
                // fl(clamp(g,-1)+1) == fmax(fl(g+1), 0):
                //   g >= -1: both fl(g+1) (>= 0);  g < -1: both +0 (incl. -0 -> +0)
                ull up = add2(gp, ONE2);          // (fl(gx+1), fl(gy+1))
                float ux, uy; upk(up, ux, uy);
                ux = fmaxf(ux, 0.0f);
                uy = fmaxf(uy, 0.0f);
                // ((g+1)*512-1)*0.5 == fma(u,256,-0.5) exactly; +MAGIC = rint(ties-even)
                ull rp = add2(fma2(pk(ux, uy), C256, MH2), MAG2);
                float rx, ry; upk(rp, rx, ry);
                bool ok = fmaxf(rx, ry) < BOUND;  // ix,iy >= 0 guaranteed by clamp
                // iy*512 + ix directly from magic bit patterns (mod 2^32)
                unsigned idx = (unsigned)__float_as_int(ry) * 512u
                             + (unsigned)__float_as_int(rx)
                             - 0x4B400000u * 513u;
                ull val = 0ull;
                if (ok) val = __ldg((const ull*)((const char*)g_xi + (size_t)idx * 8u));
                acc[j] = add2(acc[j], val);
            }
        }
    }

    // reduce over the H h-lanes of each chunk, then write
    #pragma unroll
    for (int j = 0; j < NC; j++) {
        float a0, a1; upk(acc[j], a0, a1);
        #pragma unroll
        for (int off = W; off < 32; off <<= 1) {
            a0 += __shfl_xor_sync(0xffffffffu, a0, off);
            a1 += __shfl_xor_sync(0xffffffffu, a1, off);
        }
        if (hi == 0) {
            int w = wbase + j * W + wi;
            out[v * IMG + w]               = a0 * (1.0f / 512.0f);
            out[NVIEW * IMG + v * IMG + w] = a1 * (1.0f / 512.0f);
        }
    }
}

// Single fat launch: all 180 views; per-block uniform dispatch on tile shape.
// 1440 blocks <= 10 blocks/SM * 148 SMs = 1480 slots -> single wave.
__global__ __launch_bounds__(128, 10) void radon_kernel(float* __restrict__ out, ViewShapes sh) {
    const int v = blockIdx.y;
    switch (sh.lw[v]) {
        case 2: radon_body<2>(out, v); break;
        case 3: radon_body<3>(out, v); break;
        default: radon_body<4>(out, v); break;
    }
}

extern "C" void kernel_launch(void* const* d_in, const int* in_sizes, int n_in,
                              void* d_out, int out_size) {
    const float* x = (const float*)d_in[0];
    float* out = (float*)d_out;

    prep_kernel<<<NPIX / 4 / 256, 256>>>(x);

    // Host-side per-view tile-shape selection (perf-only; any shape is correct).
    ViewShapes sh;
    for (int v = 0; v < NVIEW; v++) {
        double th = (double)v * (M_PI / 180.0);
        double ac = fabs(cos(th)), as = fabs(sin(th));
        int best = 2; double bestcost = 1e30;
        for (int lw = 2; lw <= 4; lw++) {
            double W = (double)(1 << lw), H = 32.0 / W;
            double rows = W * as + H * ac + 1.0;
            double segB = (W * ac + H * as) * 8.0 + 8.0;
            double cost = rows * (1.0 + segB / 128.0);
            if (cost < bestcost) { bestcost = cost; best = lw; }
        }
        sh.lw[v] = (unsigned char)best;
    }

    dim3 grid(IMG / 64, NVIEW);
    radon_kernel<<<grid, 128>>>(out, sh);
}

// round 8
// speedup vs baseline: 1.1573x; 1.0477x over previous
#include <cuda_runtime.h>
#include <math.h>

#define IMG   512
#define NVIEW 180
#define NPIX  (IMG * IMG)

typedef unsigned long long ull;

// Interleaved copy of both batch images: g_xi[y*512+x] = (batch0, batch1).
__device__ float2 g_xi[NPIX];

struct Params {
    float2 cs[NVIEW];            // (cos, sin) per view, fp32 from double (matches numpy)
    unsigned char lw[NVIEW];     // tile shape per view
};

// ---- packed f32x2 helpers (sm_100+) ----
__device__ __forceinline__ ull pk(float lo, float hi) {
    ull r; asm("mov.b64 %0,{%1,%2};" : "=l"(r) : "f"(lo), "f"(hi)); return r;
}
__device__ __forceinline__ void upk(ull p, float& lo, float& hi) {
    asm("mov.b64 {%0,%1},%2;" : "=f"(lo), "=f"(hi) : "l"(p));
}
__device__ __forceinline__ ull mul2(ull a, ull b) {
    ull r; asm("mul.rn.f32x2 %0,%1,%2;" : "=l"(r) : "l"(a), "l"(b)); return r;
}
__device__ __forceinline__ ull add2(ull a, ull b) {
    ull r; asm("add.rn.f32x2 %0,%1,%2;" : "=l"(r) : "l"(a), "l"(b)); return r;
}
__device__ __forceinline__ ull fma2(ull a, ull b, ull c) {
    ull r; asm("fma.rn.f32x2 %0,%1,%2,%3;" : "=l"(r) : "l"(a), "l"(b), "l"(c)); return r;
}

// Interleave prep: 4 pixels per thread, vectorized 128-bit loads/stores.
__global__ __launch_bounds__(256) void prep_kernel(const float* __restrict__ x) {
    int i = blockIdx.x * blockDim.x + threadIdx.x;           // 65536 threads
    const float4* a4 = (const float4*)x;                      // batch 0
    const float4* b4 = (const float4*)(x + NPIX);             // batch 1
    float4 a = a4[i];
    float4 b = b4[i];
    float4* o = (float4*)&g_xi[i * 4];
    o[0] = make_float4(a.x, b.x, a.y, b.y);
    o[1] = make_float4(a.z, b.z, a.w, b.w);
}

// Warp tile: W lanes along w, H = 32/W lanes along h; each warp makes 16
// outputs (NC = 16/W chunks). Outer iteration 'to' covers image rows
// [8*to, 8*to+8) for every shape; G*NC = 4 gathers in flight per thread.
// Valid-range clipping: sample invalid only when gx>1 or gy>1 (s>=0 and the
// -1 clamp maps to valid index 0). Both conditions are monotone in h, so the
// possibly-valid outer iterations form one window [to_s, to_e), computed
// conservatively per warp (skip only if ALL lanes certainly invalid).
template<int LOGW>
__device__ __forceinline__ void radon_body(float* __restrict__ out, int v, float2 cs) {
    constexpr int W  = 1 << LOGW;
    constexpr int H  = 32 >> LOGW;
    constexpr int NC = 16 / W;     // w-chunks per warp
    constexpr int G  = W / 4;      // h-steps per outer iter (G*NC == 4)

    const int lane = threadIdx.x & 31;
    const int warp = threadIdx.x >> 5;
    const int wi   = lane & (W - 1);
    const int hi   = lane >> LOGW;
    const int wbase = (blockIdx.x << 6) + (warp << 4);

    const float c = cs.x, s = cs.y;
    const ull csP  = pk(s, c);          // (s, c)
    const ull sgnP = pk(-1.0f, 1.0f);   // gx = P - s*gy0 ; gy = S + c*gy0

    ull PS[NC], acc[NC];
    #pragma unroll
    for (int j = 0; j < NC; j++) {
        int w = wbase + j * W + wi;
        float gx0 = __fmaf_rn((float)w, 1.0f / 256.0f, -511.0f / 512.0f);  // exact
        PS[j] = pk(__fmul_rn(c, gx0), __fmul_rn(s, gx0));   // (P, S)
        acc[j] = 0ull;
    }

    // ---- conservative per-warp valid window over outer iterations ----
    int to_s = 0, to_e = 64;
    {
        float gx0a = __fmaf_rn((float)wbase,        1.0f / 256.0f, -511.0f / 512.0f);
        float gx0b = __fmaf_rn((float)(wbase + 15), 1.0f / 256.0f, -511.0f / 512.0f);
        float m1 = fminf(c * gx0a, c * gx0b);   // min over lanes of c*gx0
        float M2 = fminf(s * gx0a, s * gx0b);   // min over lanes of s*gx0
        // all-gx-invalid (gx>1 for every lane) holds for to < T (gx decreasing in h)
        if (s > 1e-6f && m1 > 1.0f) {
            float T = (256.0f * (m1 - 1.0f) / s + 248.5f) * 0.125f;
            int t = (int)floorf(T) - 1;                   // margin: skip less
            if (t > to_s) to_s = t;
        }
        if (c < -1e-6f) {
            // all-gy-invalid for small to (c<0: gy decreasing in h)
            float T = (256.0f * (1.0f - M2) / c + 248.5f) * 0.125f;
            int t = (int)floorf(T) - 1;
            if (t > to_s) to_s = t;
        } else if (c > 1e-6f) {
            // all-gy-invalid for large to (c>0: gy increasing in h)
            float T = (256.0f * (1.0f - M2) / c + 255.5f) * 0.125f;
            int t = (int)ceilf(T) + 2;                    // margin: skip less
            if (t < to_e) to_e = t;
        }
        if (to_s < 0) to_s = 0;
        if (to_e > 64) to_e = 64;
        if (to_e < to_s) to_e = to_s;
    }

    // gy0 starts at h = hi + 8*to_s; all values and increments exact in fp32
    float gy0 = __fmaf_rn((float)(hi + 8 * to_s), 1.0f / 256.0f, -511.0f / 512.0f);
    ull gy0p = pk(gy0, gy0);
    const ull stepP = pk((float)H / 256.0f, (float)H / 256.0f);

    const float MAGIC = 12582912.0f;      // 1.5*2^23: magic round-half-even
    const float BOUND = 12583424.0f;      // MAGIC + 512
    const ull ONE2 = pk(1.0f, 1.0f);
    const ull C256 = pk(256.0f, 256.0f);
    const ull MH2  = pk(-0.5f, -0.5f);
    const ull MAG2 = pk(MAGIC, MAGIC);

    #pragma unroll 1
    for (int to = to_s; to < to_e; to++) {
        #pragma unroll
        for (int g = 0; g < G; g++) {
            ull qp = mul2(gy0p, csP);         // (s*gy0, c*gy0), each rounded once
            gy0p = add2(gy0p, stepP);         // exact
            #pragma unroll
            for (int j = 0; j < NC; j++) {
                ull gp = fma2(qp, sgnP, PS[j]);   // (fl(P - s*gy0), fl(S + c*gy0))
                // fl(clamp(g,-1)+1) == fmax(fl(g+1), 0)
                ull up = add2(gp, ONE2);          // (fl(gx+1), fl(gy+1))
                float ux, uy; upk(up, ux, uy);
                ux = fmaxf(ux, 0.0f);
                uy = fmaxf(uy, 0.0f);
                // ((g+1)*512-1)*0.5 == fma(u,256,-0.5) exactly; +MAGIC = rint(ties-even)
                ull rp = add2(fma2(pk(ux, uy), C256, MH2), MAG2);
                float rx, ry; upk(rp, rx, ry);
                bool ok = fmaxf(rx, ry) < BOUND;  // ix,iy >= 0 guaranteed by clamp
                // iy*512 + ix directly from magic bit patterns (mod 2^32)
                unsigned idx = (unsigned)__float_as_int(ry) * 512u
                             + (unsigned)__float_as_int(rx)
                             - 0x4B400000u * 513u;
                ull val = 0ull;
                if (ok) val = __ldg((const ull*)((const char*)g_xi + (size_t)idx * 8u));
                acc[j] = add2(acc[j], val);
            }
        }
    }

    // reduce over the H h-lanes of each chunk, then write
    #pragma unroll
    for (int j = 0; j < NC; j++) {
        float a0, a1; upk(acc[j], a0, a1);
        #pragma unroll
        for (int off = W; off < 32; off <<= 1) {
            a0 += __shfl_xor_sync(0xffffffffu, a0, off);
            a1 += __shfl_xor_sync(0xffffffffu, a1, off);
        }
        if (hi == 0) {
            int w = wbase + j * W + wi;
            out[v * IMG + w]               = a0 * (1.0f / 512.0f);
            out[NVIEW * IMG + v * IMG + w] = a1 * (1.0f / 512.0f);
        }
    }
}

// Single fat launch: all 180 views; per-block uniform dispatch on tile shape.
// 1440 blocks <= 10 blocks/SM * 148 SMs = 1480 slots -> single wave.
__global__ __launch_bounds__(128, 10) void radon_kernel(float* __restrict__ out, Params p) {
    const int v = blockIdx.y;
    const float2 cs = p.cs[v];
    switch (p.lw[v]) {
        case 2: radon_body<2>(out, v, cs); break;
        case 3: radon_body<3>(out, v, cs); break;
        default: radon_body<4>(out, v, cs); break;
    }
}

extern "C" void kernel_launch(void* const* d_in, const int* in_sizes, int n_in,
                              void* d_out, int out_size) {
    const float* x = (const float*)d_in[0];
    float* out = (float*)d_out;

    prep_kernel<<<NPIX / 4 / 256, 256>>>(x);

    // Host-side trig (exactly numpy's fp32 cast) + tile-shape selection.
    static Params p;
    for (int v = 0; v < NVIEW; v++) {
        double th = (double)v * (M_PI / 180.0);
        p.cs[v] = make_float2((float)cos(th), (float)sin(th));
        double ac = fabs(cos(th)), as = fabs(sin(th));
        int best = 2; double bestcost = 1e30;
        for (int lw = 2; lw <= 4; lw++) {
            double W = (double)(1 << lw), H = 32.0 / W;
            double rows = W * as + H * ac + 1.0;
            double segB = (W * ac + H * as) * 8.0 + 8.0;
            double cost = rows * (1.0 + segB / 128.0);
            if (cost < bestcost) { bestcost = cost; best = lw; }
        }
        p.lw[v] = (unsigned char)best;
    }

    dim3 grid(IMG / 64, NVIEW);
    radon_kernel<<<grid, 128>>>(out, p);
}